// round 2
// baseline (speedup 1.0000x reference)
#include <cuda_runtime.h>
#include <cstdint>
#include <math.h>

// Problem dims (fixed by the dataset)
#define Bn 16384
#define Dn 4096
#define Hh 32
#define HDh 128
#define EPSf 1e-5f

// GEMM tiling
#define BM 128
#define BN 128
#define BK 32
#define BKP 36   // padded K stride in smem (floats) -> conflict-free frag loads
#define TILE_FLOATS (BM * BKP)            // 4608
#define SMEM_BYTES (4 * TILE_FLOATS * 4)  // A(x2) + W(x2) = 73728 bytes

// ---------------- scratch (static device allocations; no cudaMalloc) --------
__device__ float d_g[(size_t)Bn * Dn];
__device__ float d_q[(size_t)Bn * Dn];
__device__ float d_k[(size_t)Bn * Dn];
__device__ float d_v[(size_t)Bn * Dn];
__device__ float d_xm[Bn];
__device__ float d_ym[Dn];
__device__ float d_part[64 * Dn];
__device__ float d_gx[Bn];
__device__ float d_gy[Dn];
__device__ float d_stats[4];

// ---------------- small helpers ---------------------------------------------
__device__ __forceinline__ uint32_t f2tf32(float x) {
    uint32_t r;
    asm volatile("cvt.rna.tf32.f32 %0, %1;\n" : "=r"(r) : "f"(x));
    return r;
}

__device__ __forceinline__ void cp_async16(void* smem_ptr, const void* gmem_ptr) {
    uint32_t saddr = (uint32_t)__cvta_generic_to_shared(smem_ptr);
    asm volatile("cp.async.cg.shared.global [%0], [%1], 16;\n" ::"r"(saddr), "l"(gmem_ptr));
}

__device__ __forceinline__ void mma_tf32(float* c, const uint32_t* a, const uint32_t* b) {
    asm volatile(
        "mma.sync.aligned.m16n8k8.row.col.f32.tf32.tf32.f32 "
        "{%0,%1,%2,%3}, {%4,%5,%6,%7}, {%8,%9}, {%0,%1,%2,%3};\n"
        : "+f"(c[0]), "+f"(c[1]), "+f"(c[2]), "+f"(c[3])
        : "r"(a[0]), "r"(a[1]), "r"(a[2]), "r"(a[3]), "r"(b[0]), "r"(b[1]));
}

__device__ __forceinline__ float warp_sum(float v) {
#pragma unroll
    for (int o = 16; o > 0; o >>= 1) v += __shfl_down_sync(0xffffffffu, v, o);
    return v;
}

// ---------------- stage A: reductions & gates --------------------------------
__global__ void rowmean_kernel(const float* __restrict__ x, float* __restrict__ xm) {
    __shared__ float sred[4];
    int b = blockIdx.x, t = threadIdx.x;
    size_t off = (size_t)b * Dn;
    float s = 0.f;
    for (int d = t; d < Dn; d += 128) s += x[off + d];
    s = warp_sum(s);
    if ((t & 31) == 0) sred[t >> 5] = s;
    __syncthreads();
    if (t == 0) xm[b] = (sred[0] + sred[1] + sred[2] + sred[3]) * (1.0f / Dn);
}

__global__ void colpart_kernel(const float* __restrict__ x, float* __restrict__ part) {
    int c = blockIdx.x * 128 + threadIdx.x;   // column
    int r0 = blockIdx.y * 256;                // row chunk
    float s = 0.f;
    for (int i = 0; i < 256; i++) s += x[(size_t)(r0 + i) * Dn + c];
    part[(size_t)blockIdx.y * Dn + c] = s;
}

__global__ void colfin_kernel(const float* __restrict__ part, float* __restrict__ ym) {
    int c = blockIdx.x * 128 + threadIdx.x;
    float s = 0.f;
    for (int j = 0; j < 64; j++) s += part[(size_t)j * Dn + c];
    ym[c] = s * (1.0f / Bn);
}

// block 0: stats of xm (n=Bn); block 1: stats of ym (n=Dn)
__global__ void stats_kernel(const float* __restrict__ xm, const float* __restrict__ ym,
                             const float* __restrict__ wx, const float* __restrict__ wy,
                             float* __restrict__ stats) {
    __shared__ float sA[32], sB[32];
    const float* v = (blockIdx.x == 0) ? xm : ym;
    int n = (blockIdx.x == 0) ? Bn : Dn;
    int t = threadIdx.x;
    float s = 0.f, ss = 0.f;
    for (int i = t; i < n; i += blockDim.x) {
        float u = v[i];
        s += u;
        ss += u * u;
    }
    s = warp_sum(s);
    ss = warp_sum(ss);
    if ((t & 31) == 0) { sA[t >> 5] = s; sB[t >> 5] = ss; }
    __syncthreads();
    if (t == 0) {
        float S = 0.f, SS = 0.f;
        for (int j = 0; j < (int)(blockDim.x >> 5); j++) { S += sA[j]; SS += sB[j]; }
        float mean = S / n;
        float var = SS / n - mean * mean;
        float w = (blockIdx.x == 0) ? *wx : *wy;
        // myln denom: sqrt(var_c + eps) + eps, with var_c = w^2 * var (affine shift cancels)
        float den = sqrtf(w * w * var + EPSf) + EPSf;
        stats[2 * blockIdx.x + 0] = mean;
        stats[2 * blockIdx.x + 1] = den;
    }
}

__global__ void gates_kernel(const float* __restrict__ xm, const float* __restrict__ ym,
                             const float* __restrict__ stats,
                             const float* __restrict__ wx, const float* __restrict__ wy,
                             float* __restrict__ gx, float* __restrict__ gy) {
    int i = blockIdx.x * blockDim.x + threadIdx.x;
    if (i < Bn) {
        float z = (*wx) * (xm[i] - stats[0]) / stats[1];
        gx[i] = 1.0f / (1.0f + expf(-z));
    }
    int j = i - Bn;
    if (j >= 0 && j < Dn) {
        float z = (*wy) * (ym[j] - stats[2]) / stats[3];
        gy[j] = 1.0f / (1.0f + expf(-z));
    }
}

__global__ void gmul_kernel(const float* __restrict__ x, const float* __restrict__ gx,
                            const float* __restrict__ gy, float* __restrict__ g) {
    size_t i = (size_t)blockIdx.x * blockDim.x + threadIdx.x;
    int b = (int)(i >> 12);
    int d = (int)(i & 4095);
    g[i] = x[i] * gx[b] * gy[d];
}

// ---------------- GEMM: C[M,N] = A[M,K] @ W[N,K]^T + bias --------------------
__global__ __launch_bounds__(256, 2) void gemm_nt(const float* __restrict__ A,
                                                  const float* __restrict__ W,
                                                  const float* __restrict__ bias,
                                                  float* __restrict__ C,
                                                  int M, int N, int K) {
    extern __shared__ float smem[];
    float* As[2] = {smem, smem + TILE_FLOATS};
    float* Ws[2] = {smem + 2 * TILE_FLOATS, smem + 3 * TILE_FLOATS};

    const int m0 = blockIdx.y * BM;
    const int n0 = blockIdx.x * BN;
    const int tid = threadIdx.x;
    const int wid = tid >> 5, lane = tid & 31;
    const int wm = wid >> 2, wn = wid & 3;       // warp grid 2 x 4
    const int grp = lane >> 2, tg = lane & 3;

    const int lrow = tid >> 3;          // 0..31
    const int lcol = (tid & 7) * 4;     // 0,4,..,28
    const float* Ag = A + (size_t)(m0 + lrow) * K + lcol;
    const float* Wg = W + (size_t)(n0 + lrow) * K + lcol;

    auto load_tile = [&](int buf, int k0) {
#pragma unroll
        for (int r = 0; r < 4; r++) {
            cp_async16(&As[buf][(lrow + r * 32) * BKP + lcol], Ag + (size_t)(r * 32) * K + k0);
            cp_async16(&Ws[buf][(lrow + r * 32) * BKP + lcol], Wg + (size_t)(r * 32) * K + k0);
        }
        asm volatile("cp.async.commit_group;\n" ::: "memory");
    };

    float acc[4][4][4];
#pragma unroll
    for (int mi = 0; mi < 4; mi++)
#pragma unroll
        for (int ni = 0; ni < 4; ni++)
#pragma unroll
            for (int r = 0; r < 4; r++) acc[mi][ni][r] = 0.f;

    const int nkt = K / BK;
    load_tile(0, 0);
    for (int kt = 0; kt < nkt; kt++) {
        int buf = kt & 1;
        if (kt + 1 < nkt) {
            load_tile(buf ^ 1, (kt + 1) * BK);
            asm volatile("cp.async.wait_group 1;\n" ::: "memory");
        } else {
            asm volatile("cp.async.wait_group 0;\n" ::: "memory");
        }
        __syncthreads();
        const float* Ab = As[buf];
        const float* Wb = Ws[buf];
#pragma unroll
        for (int k8 = 0; k8 < BK / 8; k8++) {
            const int kb = k8 * 8;
            uint32_t afr[4][4];
#pragma unroll
            for (int mi = 0; mi < 4; mi++) {
                int r = wm * 64 + mi * 16 + grp;
                afr[mi][0] = f2tf32(Ab[(r) * BKP + kb + tg]);
                afr[mi][1] = f2tf32(Ab[(r + 8) * BKP + kb + tg]);
                afr[mi][2] = f2tf32(Ab[(r) * BKP + kb + tg + 4]);
                afr[mi][3] = f2tf32(Ab[(r + 8) * BKP + kb + tg + 4]);
            }
            uint32_t bfr[4][2];
#pragma unroll
            for (int ni = 0; ni < 4; ni++) {
                int c = wn * 32 + ni * 8 + grp;
                bfr[ni][0] = f2tf32(Wb[c * BKP + kb + tg]);
                bfr[ni][1] = f2tf32(Wb[c * BKP + kb + tg + 4]);
            }
#pragma unroll
            for (int mi = 0; mi < 4; mi++)
#pragma unroll
                for (int ni = 0; ni < 4; ni++) mma_tf32(acc[mi][ni], afr[mi], bfr[ni]);
        }
        __syncthreads();
    }

    // epilogue: + bias, fp32 out
#pragma unroll
    for (int mi = 0; mi < 4; mi++) {
#pragma unroll
        for (int ni = 0; ni < 4; ni++) {
            int row = m0 + wm * 64 + mi * 16 + grp;
            int col = n0 + wn * 32 + ni * 8 + tg * 2;
            float b0 = bias[col], b1 = bias[col + 1];
            float2 v0 = make_float2(acc[mi][ni][0] + b0, acc[mi][ni][1] + b1);
            float2 v1 = make_float2(acc[mi][ni][2] + b0, acc[mi][ni][3] + b1);
            *(float2*)&C[(size_t)row * N + col] = v0;
            *(float2*)&C[(size_t)(row + 8) * N + col] = v1;
        }
    }
}

// ---------------- stage C: per-row scalar attention + residual + LN ----------
__global__ void attn_ln_kernel(const float* __restrict__ Q, const float* __restrict__ K,
                               const float* __restrict__ V, const float* __restrict__ G,
                               const float* __restrict__ gamma, const float* __restrict__ beta,
                               float* __restrict__ Hout) {
    __shared__ float sval[Dn];       // 16KB stash of attn+g
    __shared__ float swarp[Hh][4];
    __shared__ float sw[Hh];
    __shared__ float sredA[4], sredB[4];
    __shared__ float sstat[2];

    int b = blockIdx.x, t = threadIdx.x;
    int warp = t >> 5, lane = t & 31;
    size_t off = (size_t)b * Dn;

    // per-head scores: head i owns elements i*128 + t
#pragma unroll 1
    for (int i = 0; i < Hh; i++) {
        int d = i * HDh + t;
        float p = Q[off + d] * K[off + d];
        p = warp_sum(p);
        if (lane == 0) swarp[i][warp] = p;
    }
    __syncthreads();
    if (t < Hh) {
        float s = (swarp[t][0] + swarp[t][1] + swarp[t][2] + swarp[t][3]) * 0.08838834764831845f;
        float m = s;
#pragma unroll
        for (int o = 16; o > 0; o >>= 1) m = fmaxf(m, __shfl_xor_sync(0xffffffffu, m, o));
        float e = expf(s - m);
        float sum = e;
#pragma unroll
        for (int o = 16; o > 0; o >>= 1) sum += __shfl_xor_sync(0xffffffffu, sum, o);
        sw[t] = e / sum;
    }
    __syncthreads();

    float s1 = 0.f, s2 = 0.f;
#pragma unroll 1
    for (int i = 0; i < Hh; i++) {
        int d = i * HDh + t;
        float val = sw[i] * V[off + d] + G[off + d];
        sval[d] = val;
        s1 += val;
        s2 += val * val;
    }
    s1 = warp_sum(s1);
    s2 = warp_sum(s2);
    if (lane == 0) { sredA[warp] = s1; sredB[warp] = s2; }
    __syncthreads();
    if (t == 0) {
        float S1 = sredA[0] + sredA[1] + sredA[2] + sredA[3];
        float S2 = sredB[0] + sredB[1] + sredB[2] + sredB[3];
        float mean = S1 * (1.0f / Dn);
        float var = S2 * (1.0f / Dn) - mean * mean;
        sstat[0] = mean;
        sstat[1] = 1.0f / sqrtf(var + EPSf);
    }
    __syncthreads();
    float mean = sstat[0], rstd = sstat[1];
#pragma unroll 1
    for (int i = 0; i < Hh; i++) {
        int d = i * HDh + t;
        Hout[off + d] = (sval[d] - mean) * rstd * gamma[d] + beta[d];
    }
}

// ---------------- launch ------------------------------------------------------
extern "C" void kernel_launch(void* const* d_in, const int* in_sizes, int n_in,
                              void* d_out, int out_size) {
    const float* x = (const float*)d_in[0];
    const float* wx = (const float*)d_in[1];
    // bx (d_in[2]) and by (d_in[4]) cancel inside myln — unused.
    const float* wy = (const float*)d_in[3];
    const float* Wq = (const float*)d_in[5];
    const float* bq = (const float*)d_in[6];
    const float* Wk = (const float*)d_in[7];
    const float* bk = (const float*)d_in[8];
    const float* Wv = (const float*)d_in[9];
    const float* bv = (const float*)d_in[10];
    const float* Wo = (const float*)d_in[11];
    const float* bo = (const float*)d_in[12];
    const float* gamma = (const float*)d_in[13];
    const float* beta = (const float*)d_in[14];
    float* out = (float*)d_out;

    float *g, *q, *k, *v, *xm, *ym, *part, *gx, *gy, *stats;
    cudaGetSymbolAddress((void**)&g, d_g);
    cudaGetSymbolAddress((void**)&q, d_q);
    cudaGetSymbolAddress((void**)&k, d_k);
    cudaGetSymbolAddress((void**)&v, d_v);
    cudaGetSymbolAddress((void**)&xm, d_xm);
    cudaGetSymbolAddress((void**)&ym, d_ym);
    cudaGetSymbolAddress((void**)&part, d_part);
    cudaGetSymbolAddress((void**)&gx, d_gx);
    cudaGetSymbolAddress((void**)&gy, d_gy);
    cudaGetSymbolAddress((void**)&stats, d_stats);

    cudaFuncSetAttribute(gemm_nt, cudaFuncAttributeMaxDynamicSharedMemorySize, SMEM_BYTES);

    rowmean_kernel<<<Bn, 128>>>(x, xm);
    colpart_kernel<<<dim3(Dn / 128, 64), 128>>>(x, part);
    colfin_kernel<<<Dn / 128, 128>>>(part, ym);
    stats_kernel<<<2, 1024>>>(xm, ym, wx, wy, stats);
    gates_kernel<<<(Bn + Dn + 255) / 256, 256>>>(xm, ym, stats, wx, wy, gx, gy);
    gmul_kernel<<<(int)(((size_t)Bn * Dn) / 256), 256>>>(x, gx, gy, g);

    dim3 gg(Dn / BN, Bn / BM);
    gemm_nt<<<gg, 256, SMEM_BYTES>>>(g, Wq, bq, q, Bn, Dn, Dn);
    gemm_nt<<<gg, 256, SMEM_BYTES>>>(g, Wk, bk, k, Bn, Dn, Dn);
    gemm_nt<<<gg, 256, SMEM_BYTES>>>(g, Wv, bv, v, Bn, Dn, Dn);

    // h aliases q: each block reads its own row of q before overwriting it.
    attn_ln_kernel<<<Bn, 128>>>(q, k, v, g, gamma, beta, q);

    gemm_nt<<<gg, 256, SMEM_BYTES>>>(q, Wo, bo, out, Bn, Dn, Dn);
}

// round 4
// speedup vs baseline: 2.4700x; 2.4700x over previous
#include <cuda_runtime.h>
#include <cuda_fp16.h>
#include <cstdint>
#include <math.h>

// Problem dims (fixed by the dataset)
#define Bn 16384
#define Dn 4096
#define Hh 32
#define HDh 128
#define EPSf 1e-5f

// ---- fp16 mma.sync GEMM tiling ----------------------------------------------
#define BM 128
#define BN 256
#define BKh 64                 // K elements (fp16) per stage => 128 bytes/row
#define STG 4
#define ROWB 128               // bytes per smem row
#define AST (BM * ROWB)        // 16384
#define BST (BN * ROWB)        // 32768
#define STAGE_B (AST + BST)    // 49152
#define SMEMB (STG * STAGE_B + 1024)  // 197632 (align slack)
#define NKT (4096 / BKh)       // 64

// ---------------- scratch (static device allocations; no cudaMalloc) --------
__device__ float d_g[(size_t)Bn * Dn];
__device__ __half d_g16[(size_t)Bn * Dn];
__device__ __half d_h16[(size_t)Bn * Dn];
__device__ float d_q[(size_t)Bn * Dn];
__device__ float d_k[(size_t)Bn * Dn];
__device__ float d_v[(size_t)Bn * Dn];
__device__ __half d_wq16[(size_t)Dn * Dn];
__device__ __half d_wk16[(size_t)Dn * Dn];
__device__ __half d_wv16[(size_t)Dn * Dn];
__device__ __half d_wo16[(size_t)Dn * Dn];
__device__ float d_xm[Bn];
__device__ float d_ym[Dn];
__device__ float d_part[64 * Dn];
__device__ float d_gx[Bn];
__device__ float d_gy[Dn];
__device__ float d_stats[4];

// ---------------- helpers -----------------------------------------------------
__device__ __forceinline__ uint32_t smem_u32(const void* p) {
    uint32_t a;
    asm("{ .reg .u64 t; cvta.to.shared.u64 t, %1; cvt.u32.u64 %0, t; }" : "=r"(a) : "l"(p));
    return a;
}
__device__ __forceinline__ void cp_async16(uint32_t saddr, const void* gptr) {
    asm volatile("cp.async.cg.shared.global [%0], [%1], 16;\n" ::"r"(saddr), "l"(gptr));
}
#define LDSM_X4(r, addr)                                                        \
    asm volatile("ldmatrix.sync.aligned.m8n8.x4.shared.b16 {%0,%1,%2,%3}, [%4];" \
                 : "=r"((r)[0]), "=r"((r)[1]), "=r"((r)[2]), "=r"((r)[3])       \
                 : "r"(addr))
__device__ __forceinline__ void mma_h(float* c, const uint32_t* a, uint32_t b0, uint32_t b1) {
    asm volatile(
        "mma.sync.aligned.m16n8k16.row.col.f32.f16.f16.f32 "
        "{%0,%1,%2,%3}, {%4,%5,%6,%7}, {%8,%9}, {%0,%1,%2,%3};\n"
        : "+f"(c[0]), "+f"(c[1]), "+f"(c[2]), "+f"(c[3])
        : "r"(a[0]), "r"(a[1]), "r"(a[2]), "r"(a[3]), "r"(b0), "r"(b1));
}
__device__ __forceinline__ float warp_sum(float v) {
#pragma unroll
    for (int o = 16; o > 0; o >>= 1) v += __shfl_down_sync(0xffffffffu, v, o);
    return v;
}

// ---------------- stage A: reductions & gates --------------------------------
__global__ void rowmean_kernel(const float* __restrict__ x, float* __restrict__ xm) {
    __shared__ float sred[4];
    int b = blockIdx.x, t = threadIdx.x;
    size_t off = (size_t)b * Dn;
    float s = 0.f;
    for (int d = t; d < Dn; d += 128) s += x[off + d];
    s = warp_sum(s);
    if ((t & 31) == 0) sred[t >> 5] = s;
    __syncthreads();
    if (t == 0) xm[b] = (sred[0] + sred[1] + sred[2] + sred[3]) * (1.0f / Dn);
}

__global__ void colpart_kernel(const float* __restrict__ x, float* __restrict__ part) {
    int c = blockIdx.x * 128 + threadIdx.x;
    int r0 = blockIdx.y * 256;
    float s = 0.f;
    for (int i = 0; i < 256; i++) s += x[(size_t)(r0 + i) * Dn + c];
    part[(size_t)blockIdx.y * Dn + c] = s;
}

__global__ void colfin_kernel(const float* __restrict__ part, float* __restrict__ ym) {
    int c = blockIdx.x * 128 + threadIdx.x;
    float s = 0.f;
    for (int j = 0; j < 64; j++) s += part[(size_t)j * Dn + c];
    ym[c] = s * (1.0f / Bn);
}

__global__ void stats_kernel(const float* __restrict__ xm, const float* __restrict__ ym,
                             const float* __restrict__ wx, const float* __restrict__ wy,
                             float* __restrict__ stats) {
    __shared__ float sA[32], sB[32];
    const float* v = (blockIdx.x == 0) ? xm : ym;
    int n = (blockIdx.x == 0) ? Bn : Dn;
    int t = threadIdx.x;
    float s = 0.f, ss = 0.f;
    for (int i = t; i < n; i += blockDim.x) {
        float u = v[i];
        s += u;
        ss += u * u;
    }
    s = warp_sum(s);
    ss = warp_sum(ss);
    if ((t & 31) == 0) { sA[t >> 5] = s; sB[t >> 5] = ss; }
    __syncthreads();
    if (t == 0) {
        float S = 0.f, SS = 0.f;
        for (int j = 0; j < (int)(blockDim.x >> 5); j++) { S += sA[j]; SS += sB[j]; }
        float mean = S / n;
        float var = SS / n - mean * mean;
        float w = (blockIdx.x == 0) ? *wx : *wy;
        float den = sqrtf(w * w * var + EPSf) + EPSf;
        stats[2 * blockIdx.x + 0] = mean;
        stats[2 * blockIdx.x + 1] = den;
    }
}

__global__ void gates_kernel(const float* __restrict__ xm, const float* __restrict__ ym,
                             const float* __restrict__ stats,
                             const float* __restrict__ wx, const float* __restrict__ wy,
                             float* __restrict__ gx, float* __restrict__ gy) {
    int i = blockIdx.x * blockDim.x + threadIdx.x;
    if (i < Bn) {
        float z = (*wx) * (xm[i] - stats[0]) / stats[1];
        gx[i] = 1.0f / (1.0f + expf(-z));
    }
    int j = i - Bn;
    if (j >= 0 && j < Dn) {
        float z = (*wy) * (ym[j] - stats[2]) / stats[3];
        gy[j] = 1.0f / (1.0f + expf(-z));
    }
}

// g (fp32, for residual) and g16 (fp16 GEMM operand)
__global__ void gmul_kernel(const float* __restrict__ x, const float* __restrict__ gx,
                            const float* __restrict__ gy, float* __restrict__ g,
                            __half* __restrict__ g16) {
    size_t i = (size_t)blockIdx.x * blockDim.x + threadIdx.x;
    int b = (int)(i >> 12);
    int d = (int)(i & 4095);
    float v = x[i] * gx[b] * gy[d];
    g[i] = v;
    g16[i] = __float2half(v);
}

// fp32 -> fp16 weight conversion (vectorized)
__global__ void f2h_kernel(const float4* __restrict__ src, __half2* __restrict__ dst) {
    size_t i = (size_t)blockIdx.x * blockDim.x + threadIdx.x;
    float4 v = src[i];
    dst[2 * i] = __floats2half2_rn(v.x, v.y);
    dst[2 * i + 1] = __floats2half2_rn(v.z, v.w);
}

// ---------------- fp16 tensor-core GEMM: C[M,4096] = A @ W^T + bias ----------
__global__ __launch_bounds__(256, 1) void gemm_h(const __half* __restrict__ A,
                                                 const __half* __restrict__ W,
                                                 const float* __restrict__ bias,
                                                 float* __restrict__ C) {
    extern __shared__ char smem[];
    const uint32_t sbase = (smem_u32(smem) + 1023u) & ~1023u;
    const int tid = threadIdx.x;
    const int wid = tid >> 5, lane = tid & 31;
    const int wm = wid >> 2, wn = wid & 3;     // warp grid 2 x 4 -> 64x64 per warp
    const int grp = lane >> 2, tg = lane & 3;
    const int m0 = blockIdx.y * BM;
    const int n0 = blockIdx.x * BN;

    auto load_tile = [&](int s, int k0) {
        uint32_t sA = sbase + s * STAGE_B;
        uint32_t sB = sA + AST;
#pragma unroll
        for (int i = 0; i < 4; i++) {                 // A: 1024 chunks of 16B
            int c = tid + i * 256;
            int row = c >> 3, kc = c & 7;
            uint32_t off = row * ROWB + ((kc << 4) ^ ((row & 7) << 4));
            cp_async16(sA + off, A + (size_t)(m0 + row) * 4096 + k0 + kc * 8);
        }
#pragma unroll
        for (int i = 0; i < 8; i++) {                 // B: 2048 chunks of 16B
            int c = tid + i * 256;
            int row = c >> 3, kc = c & 7;
            uint32_t off = row * ROWB + ((kc << 4) ^ ((row & 7) << 4));
            cp_async16(sB + off, W + (size_t)(n0 + row) * 4096 + k0 + kc * 8);
        }
        asm volatile("cp.async.commit_group;\n" ::: "memory");
    };

    float acc[4][8][4];
#pragma unroll
    for (int mi = 0; mi < 4; mi++)
#pragma unroll
        for (int ni = 0; ni < 8; ni++)
#pragma unroll
            for (int r = 0; r < 4; r++) acc[mi][ni][r] = 0.f;

    // prologue: fill STG-1 stages
#pragma unroll
    for (int s = 0; s < STG - 1; s++) load_tile(s, s * BKh);

    for (int kt = 0; kt < NKT; kt++) {
        int nxt = kt + STG - 1;
        if (nxt < NKT)
            load_tile(nxt & (STG - 1), nxt * BKh);
        else
            asm volatile("cp.async.commit_group;\n" ::: "memory");
        asm volatile("cp.async.wait_group %0;\n" ::"n"(STG - 2) : "memory");
        __syncthreads();

        const int s = kt & (STG - 1);
        uint32_t sA = sbase + s * STAGE_B;
        uint32_t sB = sA + AST;
#pragma unroll
        for (int step = 0; step < 4; step++) {
            const int kb2 = step * 32;  // byte offset of k16 block
            const uint32_t kx = kb2 + ((lane >> 4) << 4);
            uint32_t afr[4][4], bfr[4][4];
#pragma unroll
            for (int mi = 0; mi < 4; mi++) {
                int row = wm * 64 + mi * 16 + (lane & 15);
                LDSM_X4(afr[mi], sA + row * ROWB + (kx ^ ((row & 7) << 4)));
            }
#pragma unroll
            for (int p = 0; p < 4; p++) {
                int row = wn * 64 + p * 16 + (lane & 15);
                LDSM_X4(bfr[p], sB + row * ROWB + (kx ^ ((row & 7) << 4)));
            }
#pragma unroll
            for (int mi = 0; mi < 4; mi++)
#pragma unroll
                for (int ni = 0; ni < 8; ni++) {
                    int p = ni >> 1, hi = ni & 1;
                    mma_h(acc[mi][ni], afr[mi], bfr[p][hi], bfr[p][hi + 2]);
                }
        }
        __syncthreads();
    }

    // epilogue: + bias, fp32 out
#pragma unroll
    for (int mi = 0; mi < 4; mi++) {
#pragma unroll
        for (int ni = 0; ni < 8; ni++) {
            int row = m0 + wm * 64 + mi * 16 + grp;
            int col = n0 + wn * 64 + ni * 8 + tg * 2;
            float b0 = __ldg(bias + col), b1 = __ldg(bias + col + 1);
            float2 v0 = make_float2(acc[mi][ni][0] + b0, acc[mi][ni][1] + b1);
            float2 v1 = make_float2(acc[mi][ni][2] + b0, acc[mi][ni][3] + b1);
            *(float2*)&C[(size_t)row * Dn + col] = v0;
            *(float2*)&C[(size_t)(row + 8) * Dn + col] = v1;
        }
    }
}

// ---------------- stage C: per-row scalar attention + residual + LN ----------
__global__ void attn_ln_kernel(const float* __restrict__ Q, const float* __restrict__ K,
                               const float* __restrict__ V, const float* __restrict__ G,
                               const float* __restrict__ gamma, const float* __restrict__ beta,
                               __half* __restrict__ Hout) {
    __shared__ float sval[Dn];
    __shared__ float swarp[Hh][4];
    __shared__ float sw[Hh];
    __shared__ float sredA[4], sredB[4];
    __shared__ float sstat[2];

    int b = blockIdx.x, t = threadIdx.x;
    int warp = t >> 5, lane = t & 31;
    size_t off = (size_t)b * Dn;

#pragma unroll 1
    for (int i = 0; i < Hh; i++) {
        int d = i * HDh + t;
        float p = Q[off + d] * K[off + d];
        p = warp_sum(p);
        if (lane == 0) swarp[i][warp] = p;
    }
    __syncthreads();
    if (t < Hh) {
        float s = (swarp[t][0] + swarp[t][1] + swarp[t][2] + swarp[t][3]) * 0.08838834764831845f;
        float m = s;
#pragma unroll
        for (int o = 16; o > 0; o >>= 1) m = fmaxf(m, __shfl_xor_sync(0xffffffffu, m, o));
        float e = expf(s - m);
        float sum = e;
#pragma unroll
        for (int o = 16; o > 0; o >>= 1) sum += __shfl_xor_sync(0xffffffffu, sum, o);
        sw[t] = e / sum;
    }
    __syncthreads();

    float s1 = 0.f, s2 = 0.f;
#pragma unroll 1
    for (int i = 0; i < Hh; i++) {
        int d = i * HDh + t;
        float val = sw[i] * V[off + d] + G[off + d];
        sval[d] = val;
        s1 += val;
        s2 += val * val;
    }
    s1 = warp_sum(s1);
    s2 = warp_sum(s2);
    if (lane == 0) { sredA[warp] = s1; sredB[warp] = s2; }
    __syncthreads();
    if (t == 0) {
        float S1 = sredA[0] + sredA[1] + sredA[2] + sredA[3];
        float S2 = sredB[0] + sredB[1] + sredB[2] + sredB[3];
        float mean = S1 * (1.0f / Dn);
        float var = S2 * (1.0f / Dn) - mean * mean;
        sstat[0] = mean;
        sstat[1] = 1.0f / sqrtf(var + EPSf);
    }
    __syncthreads();
    float mean = sstat[0], rstd = sstat[1];
#pragma unroll 1
    for (int i = 0; i < Hh; i++) {
        int d = i * HDh + t;
        Hout[off + d] = __float2half((sval[d] - mean) * rstd * gamma[d] + beta[d]);
    }
}

// ---------------- launch ------------------------------------------------------
extern "C" void kernel_launch(void* const* d_in, const int* in_sizes, int n_in,
                              void* d_out, int out_size) {
    const float* x = (const float*)d_in[0];
    const float* wx = (const float*)d_in[1];
    const float* wy = (const float*)d_in[3];
    const float* Wq = (const float*)d_in[5];
    const float* bq = (const float*)d_in[6];
    const float* Wk = (const float*)d_in[7];
    const float* bk = (const float*)d_in[8];
    const float* Wv = (const float*)d_in[9];
    const float* bv = (const float*)d_in[10];
    const float* Wo = (const float*)d_in[11];
    const float* bo = (const float*)d_in[12];
    const float* gamma = (const float*)d_in[13];
    const float* beta = (const float*)d_in[14];
    float* out = (float*)d_out;

    float *g, *q, *k, *v, *xm, *ym, *part, *gx, *gy, *stats;
    __half *g16, *h16, *wq16, *wk16, *wv16, *wo16;
    cudaGetSymbolAddress((void**)&g, d_g);
    cudaGetSymbolAddress((void**)&g16, d_g16);
    cudaGetSymbolAddress((void**)&h16, d_h16);
    cudaGetSymbolAddress((void**)&q, d_q);
    cudaGetSymbolAddress((void**)&k, d_k);
    cudaGetSymbolAddress((void**)&v, d_v);
    cudaGetSymbolAddress((void**)&wq16, d_wq16);
    cudaGetSymbolAddress((void**)&wk16, d_wk16);
    cudaGetSymbolAddress((void**)&wv16, d_wv16);
    cudaGetSymbolAddress((void**)&wo16, d_wo16);
    cudaGetSymbolAddress((void**)&xm, d_xm);
    cudaGetSymbolAddress((void**)&ym, d_ym);
    cudaGetSymbolAddress((void**)&part, d_part);
    cudaGetSymbolAddress((void**)&gx, d_gx);
    cudaGetSymbolAddress((void**)&gy, d_gy);
    cudaGetSymbolAddress((void**)&stats, d_stats);

    cudaFuncSetAttribute(gemm_h, cudaFuncAttributeMaxDynamicSharedMemorySize, SMEMB);

    // weight conversions (fp32 -> fp16), 16.7M elems each
    const int n4 = (Dn * Dn) / 4;
    f2h_kernel<<<n4 / 256, 256>>>((const float4*)Wq, (__half2*)wq16);
    f2h_kernel<<<n4 / 256, 256>>>((const float4*)Wk, (__half2*)wk16);
    f2h_kernel<<<n4 / 256, 256>>>((const float4*)Wv, (__half2*)wv16);
    f2h_kernel<<<n4 / 256, 256>>>((const float4*)Wo, (__half2*)wo16);

    rowmean_kernel<<<Bn, 128>>>(x, xm);
    colpart_kernel<<<dim3(Dn / 128, 64), 128>>>(x, part);
    colfin_kernel<<<Dn / 128, 128>>>(part, ym);
    stats_kernel<<<2, 1024>>>(xm, ym, wx, wy, stats);
    gates_kernel<<<(Bn + Dn + 255) / 256, 256>>>(xm, ym, stats, wx, wy, gx, gy);
    gmul_kernel<<<(int)(((size_t)Bn * Dn) / 256), 256>>>(x, gx, gy, g, g16);

    dim3 gg(Dn / BN, Bn / BM);  // (16, 128)
    gemm_h<<<gg, 256, SMEMB>>>(g16, wq16, bq, q);
    gemm_h<<<gg, 256, SMEMB>>>(g16, wk16, bk, k);
    gemm_h<<<gg, 256, SMEMB>>>(g16, wv16, bv, v);

    attn_ln_kernel<<<Bn, 128>>>(q, k, v, g, gamma, beta, h16);

    gemm_h<<<gg, 256, SMEMB>>>(h16, wo16, bo, out);
}

// round 5
// speedup vs baseline: 2.6675x; 1.0800x over previous
#include <cuda_runtime.h>
#include <cuda_fp16.h>
#include <cstdint>
#include <math.h>

// Problem dims (fixed by the dataset)
#define Bn 16384
#define Dn 4096
#define Hh 32
#define HDh 128
#define EPSf 1e-5f

// ---- fp16 mma.sync GEMM tiling (2 CTA/SM) -----------------------------------
#define BM 128
#define BN 128
#define BKh 64                 // K elements (fp16) per stage => 128 bytes/row
#define STG 3
#define ROWB 128               // bytes per smem row
#define AST (BM * ROWB)        // 16384
#define BST (BN * ROWB)        // 16384
#define STAGE_B (AST + BST)    // 32768
#define SMEMB (STG * STAGE_B + 1024)  // 99328
#define NKT (4096 / BKh)       // 64

// ---------------- scratch (static device allocations; no cudaMalloc) --------
__device__ float d_g[(size_t)Bn * Dn];
__device__ __half d_g16[(size_t)Bn * Dn];
__device__ __half d_h16[(size_t)Bn * Dn];
__device__ float d_q[(size_t)Bn * Dn];
__device__ float d_k[(size_t)Bn * Dn];
__device__ float d_v[(size_t)Bn * Dn];
__device__ __half d_w16[4][(size_t)Dn * Dn];
__device__ float d_xm[Bn];
__device__ float d_ym[Dn];
__device__ float d_part[64 * Dn];
__device__ float d_stats[4];

// ---------------- helpers -----------------------------------------------------
__device__ __forceinline__ uint32_t smem_u32(const void* p) {
    uint32_t a;
    asm("{ .reg .u64 t; cvta.to.shared.u64 t, %1; cvt.u32.u64 %0, t; }" : "=r"(a) : "l"(p));
    return a;
}
__device__ __forceinline__ void cp_async16(uint32_t saddr, const void* gptr) {
    asm volatile("cp.async.cg.shared.global [%0], [%1], 16;\n" ::"r"(saddr), "l"(gptr));
}
#define LDSM_X4(r, addr)                                                         \
    asm volatile("ldmatrix.sync.aligned.m8n8.x4.shared.b16 {%0,%1,%2,%3}, [%4];" \
                 : "=r"((r)[0]), "=r"((r)[1]), "=r"((r)[2]), "=r"((r)[3])        \
                 : "r"(addr))
__device__ __forceinline__ void mma_h(float* c, const uint32_t* a, uint32_t b0, uint32_t b1) {
    asm volatile(
        "mma.sync.aligned.m16n8k16.row.col.f32.f16.f16.f32 "
        "{%0,%1,%2,%3}, {%4,%5,%6,%7}, {%8,%9}, {%0,%1,%2,%3};\n"
        : "+f"(c[0]), "+f"(c[1]), "+f"(c[2]), "+f"(c[3])
        : "r"(a[0]), "r"(a[1]), "r"(a[2]), "r"(a[3]), "r"(b0), "r"(b1));
}
__device__ __forceinline__ float warp_sum(float v) {
#pragma unroll
    for (int o = 16; o > 0; o >>= 1) v += __shfl_down_sync(0xffffffffu, v, o);
    return v;
}

// ---- L1: all 4 weight conversions in one kernel ------------------------------
__global__ void f2h_all_kernel(const float4* __restrict__ w0, const float4* __restrict__ w1,
                               const float4* __restrict__ w2, const float4* __restrict__ w3,
                               __half2* __restrict__ dst) {
    const float4* srcs[4] = {w0, w1, w2, w3};
    const float4* src = srcs[blockIdx.y];
    __half2* d = dst + (size_t)blockIdx.y * ((size_t)Dn * Dn / 2);
    size_t i = (size_t)blockIdx.x * blockDim.x + threadIdx.x;
    float4 v = src[i];
    d[2 * i] = __floats2half2_rn(v.x, v.y);
    d[2 * i + 1] = __floats2half2_rn(v.z, v.w);
}

// ---- L2: rowmean (blocks 0..16383) + colpart (blocks 16384..18431) ----------
__global__ void rowcol_kernel(const float* __restrict__ x, float* __restrict__ xm,
                              float* __restrict__ part) {
    __shared__ float sred[4];
    int t = threadIdx.x;
    if (blockIdx.x < Bn) {
        int b = blockIdx.x;
        size_t off = (size_t)b * Dn;
        float s = 0.f;
        for (int d = t; d < Dn; d += 128) s += x[off + d];
        s = warp_sum(s);
        if ((t & 31) == 0) sred[t >> 5] = s;
        __syncthreads();
        if (t == 0) xm[b] = (sred[0] + sred[1] + sred[2] + sred[3]) * (1.0f / Dn);
    } else {
        int j = blockIdx.x - Bn;       // 0..2047
        int c = (j & 31) * 128 + t;    // column
        int r0 = (j >> 5) * 256;       // row chunk
        float s = 0.f;
        for (int i = 0; i < 256; i++) s += x[(size_t)(r0 + i) * Dn + c];
        part[(size_t)(j >> 5) * Dn + c] = s;
    }
}

// ---- L3: colfin (blocks 0..31) + xm stats (block 32) ------------------------
__global__ void colfin_xmstats_kernel(const float* __restrict__ part, float* __restrict__ ym,
                                      const float* __restrict__ xm, const float* __restrict__ wx,
                                      float* __restrict__ stats) {
    int t = threadIdx.x;
    if (blockIdx.x < 32) {
        int c = blockIdx.x * 128 + t;
        float s = 0.f;
        for (int j = 0; j < 64; j++) s += part[(size_t)j * Dn + c];
        ym[c] = s * (1.0f / Bn);
    } else {
        __shared__ float sA[4], sB[4];
        float s = 0.f, ss = 0.f;
        for (int i = t; i < Bn; i += 128) {
            float u = xm[i];
            s += u;
            ss += u * u;
        }
        s = warp_sum(s);
        ss = warp_sum(ss);
        if ((t & 31) == 0) { sA[t >> 5] = s; sB[t >> 5] = ss; }
        __syncthreads();
        if (t == 0) {
            float S = sA[0] + sA[1] + sA[2] + sA[3];
            float SS = sB[0] + sB[1] + sB[2] + sB[3];
            float mean = S * (1.0f / Bn);
            float var = SS * (1.0f / Bn) - mean * mean;
            float w = *wx;
            stats[0] = mean;
            stats[1] = sqrtf(w * w * var + EPSf) + EPSf;
        }
    }
}

// ---- L4: ym stats ------------------------------------------------------------
__global__ void ymstats_kernel(const float* __restrict__ ym, const float* __restrict__ wy,
                               float* __restrict__ stats) {
    __shared__ float sA[8], sB[8];
    int t = threadIdx.x;
    float s = 0.f, ss = 0.f;
    for (int i = t; i < Dn; i += 256) {
        float u = ym[i];
        s += u;
        ss += u * u;
    }
    s = warp_sum(s);
    ss = warp_sum(ss);
    if ((t & 31) == 0) { sA[t >> 5] = s; sB[t >> 5] = ss; }
    __syncthreads();
    if (t == 0) {
        float S = 0.f, SS = 0.f;
        for (int j = 0; j < 8; j++) { S += sA[j]; SS += sB[j]; }
        float mean = S * (1.0f / Dn);
        float var = SS * (1.0f / Dn) - mean * mean;
        float w = *wy;
        stats[2] = mean;
        stats[3] = sqrtf(w * w * var + EPSf) + EPSf;
    }
}

// ---- L5: gated multiply with inline sigmoid gates ----------------------------
__global__ void gmul_kernel(const float* __restrict__ x, const float* __restrict__ xm,
                            const float* __restrict__ ym, const float* __restrict__ stats,
                            const float* __restrict__ wxp, const float* __restrict__ wyp,
                            float* __restrict__ g, __half* __restrict__ g16) {
    size_t i4 = (size_t)blockIdx.x * blockDim.x + threadIdx.x;   // float4 index
    int b = (int)(i4 >> 10);                                     // 1024 float4 per row
    int d = (int)((i4 & 1023) << 2);
    float zx = (*wxp) * (xm[b] - stats[0]) / stats[1];
    float gxv = 1.0f / (1.0f + expf(-zx));
    float wy = *wyp, m2 = stats[2], d2 = stats[3];
    float4 xv = *(const float4*)(x + ((size_t)b << 12) + d);
    float4 gv;
    gv.x = xv.x * gxv / (1.0f + expf(-wy * (ym[d + 0] - m2) / d2));
    gv.y = xv.y * gxv / (1.0f + expf(-wy * (ym[d + 1] - m2) / d2));
    gv.z = xv.z * gxv / (1.0f + expf(-wy * (ym[d + 2] - m2) / d2));
    gv.w = xv.w * gxv / (1.0f + expf(-wy * (ym[d + 3] - m2) / d2));
    *(float4*)(g + ((size_t)b << 12) + d) = gv;
    *(__half2*)(g16 + ((size_t)b << 12) + d) = __floats2half2_rn(gv.x, gv.y);
    *(__half2*)(g16 + ((size_t)b << 12) + d + 2) = __floats2half2_rn(gv.z, gv.w);
}

// ---------------- fp16 tensor-core GEMM: C[M,4096] = A @ W^T + bias ----------
__global__ __launch_bounds__(256, 2) void gemm_h(const __half* __restrict__ A,
                                                 const __half* __restrict__ W,
                                                 const float* __restrict__ bias,
                                                 float* __restrict__ C) {
    extern __shared__ char smem[];
    const uint32_t sbase = (smem_u32(smem) + 1023u) & ~1023u;
    const int tid = threadIdx.x;
    const int wid = tid >> 5, lane = tid & 31;
    const int wm = wid >> 2, wn = wid & 3;     // warp grid 2 x 4 -> 64x32 per warp
    const int grp = lane >> 2, tg = lane & 3;
    const int m0 = blockIdx.y * BM;
    const int n0 = blockIdx.x * BN;

    auto load_tile = [&](int s, int k0) {
        uint32_t sA = sbase + s * STAGE_B;
        uint32_t sB = sA + AST;
#pragma unroll
        for (int i = 0; i < 4; i++) {                 // A: 1024 chunks of 16B
            int c = tid + i * 256;
            int row = c >> 3, kc = c & 7;
            uint32_t off = row * ROWB + ((kc << 4) ^ ((row & 7) << 4));
            cp_async16(sA + off, A + (size_t)(m0 + row) * 4096 + k0 + kc * 8);
        }
#pragma unroll
        for (int i = 0; i < 4; i++) {                 // B: 1024 chunks of 16B
            int c = tid + i * 256;
            int row = c >> 3, kc = c & 7;
            uint32_t off = row * ROWB + ((kc << 4) ^ ((row & 7) << 4));
            cp_async16(sB + off, W + (size_t)(n0 + row) * 4096 + k0 + kc * 8);
        }
        asm volatile("cp.async.commit_group;\n" ::: "memory");
    };

    float acc[4][4][4];
#pragma unroll
    for (int mi = 0; mi < 4; mi++)
#pragma unroll
        for (int ni = 0; ni < 4; ni++)
#pragma unroll
            for (int r = 0; r < 4; r++) acc[mi][ni][r] = 0.f;

    load_tile(0, 0);
    load_tile(1, BKh);

    int load_st = 2;   // next stage slot to fill
    int comp_st = 0;   // stage to compute
    for (int kt = 0; kt < NKT; kt++) {
        int nxt = kt + STG - 1;
        if (nxt < NKT) {
            load_tile(load_st, nxt * BKh);
            if (++load_st == STG) load_st = 0;
        } else {
            asm volatile("cp.async.commit_group;\n" ::: "memory");
        }
        asm volatile("cp.async.wait_group %0;\n" ::"n"(STG - 2) : "memory");
        __syncthreads();

        uint32_t sA = sbase + comp_st * STAGE_B;
        uint32_t sB = sA + AST;
#pragma unroll
        for (int step = 0; step < 4; step++) {
            const uint32_t kx = step * 32 + ((lane >> 4) << 4);
            uint32_t afr[4][4], bfr[2][4];
#pragma unroll
            for (int mi = 0; mi < 4; mi++) {
                int row = wm * 64 + mi * 16 + (lane & 15);
                LDSM_X4(afr[mi], sA + row * ROWB + (kx ^ ((row & 7) << 4)));
            }
#pragma unroll
            for (int p = 0; p < 2; p++) {
                int row = wn * 32 + p * 16 + (lane & 15);
                LDSM_X4(bfr[p], sB + row * ROWB + (kx ^ ((row & 7) << 4)));
            }
#pragma unroll
            for (int mi = 0; mi < 4; mi++)
#pragma unroll
                for (int ni = 0; ni < 4; ni++) {
                    int p = ni >> 1, hi = ni & 1;
                    mma_h(acc[mi][ni], afr[mi], bfr[p][hi], bfr[p][hi + 2]);
                }
        }
        __syncthreads();
        if (++comp_st == STG) comp_st = 0;
    }

    // epilogue: + bias, fp32 out
#pragma unroll
    for (int mi = 0; mi < 4; mi++) {
#pragma unroll
        for (int ni = 0; ni < 4; ni++) {
            int row = m0 + wm * 64 + mi * 16 + grp;
            int col = n0 + wn * 32 + ni * 8 + tg * 2;
            float b0 = __ldg(bias + col), b1 = __ldg(bias + col + 1);
            float2 v0 = make_float2(acc[mi][ni][0] + b0, acc[mi][ni][1] + b1);
            float2 v1 = make_float2(acc[mi][ni][2] + b0, acc[mi][ni][3] + b1);
            *(float2*)&C[(size_t)row * Dn + col] = v0;
            *(float2*)&C[(size_t)(row + 8) * Dn + col] = v1;
        }
    }
}

// ---------------- stage C: per-row scalar attention + residual + LN ----------
__global__ void attn_ln_kernel(const float* __restrict__ Q, const float* __restrict__ K,
                               const float* __restrict__ V, const float* __restrict__ G,
                               const float* __restrict__ gamma, const float* __restrict__ beta,
                               __half* __restrict__ Hout) {
    __shared__ float sval[Dn];
    __shared__ float swarp[Hh][4];
    __shared__ float sw[Hh];
    __shared__ float sredA[4], sredB[4];
    __shared__ float sstat[2];

    int b = blockIdx.x, t = threadIdx.x;
    int warp = t >> 5, lane = t & 31;
    size_t off = (size_t)b * Dn;

#pragma unroll 1
    for (int i = 0; i < Hh; i++) {
        int d = i * HDh + t;
        float p = Q[off + d] * K[off + d];
        p = warp_sum(p);
        if (lane == 0) swarp[i][warp] = p;
    }
    __syncthreads();
    if (t < Hh) {
        float s = (swarp[t][0] + swarp[t][1] + swarp[t][2] + swarp[t][3]) * 0.08838834764831845f;
        float m = s;
#pragma unroll
        for (int o = 16; o > 0; o >>= 1) m = fmaxf(m, __shfl_xor_sync(0xffffffffu, m, o));
        float e = expf(s - m);
        float sum = e;
#pragma unroll
        for (int o = 16; o > 0; o >>= 1) sum += __shfl_xor_sync(0xffffffffu, sum, o);
        sw[t] = e / sum;
    }
    __syncthreads();

    float s1 = 0.f, s2 = 0.f;
#pragma unroll 1
    for (int i = 0; i < Hh; i++) {
        int d = i * HDh + t;
        float val = sw[i] * V[off + d] + G[off + d];
        sval[d] = val;
        s1 += val;
        s2 += val * val;
    }
    s1 = warp_sum(s1);
    s2 = warp_sum(s2);
    if (lane == 0) { sredA[warp] = s1; sredB[warp] = s2; }
    __syncthreads();
    if (t == 0) {
        float S1 = sredA[0] + sredA[1] + sredA[2] + sredA[3];
        float S2 = sredB[0] + sredB[1] + sredB[2] + sredB[3];
        float mean = S1 * (1.0f / Dn);
        float var = S2 * (1.0f / Dn) - mean * mean;
        sstat[0] = mean;
        sstat[1] = 1.0f / sqrtf(var + EPSf);
    }
    __syncthreads();
    float mean = sstat[0], rstd = sstat[1];
#pragma unroll 1
    for (int i = 0; i < Hh; i++) {
        int d = i * HDh + t;
        Hout[off + d] = __float2half((sval[d] - mean) * rstd * gamma[d] + beta[d]);
    }
}

// ---------------- launch ------------------------------------------------------
extern "C" void kernel_launch(void* const* d_in, const int* in_sizes, int n_in,
                              void* d_out, int out_size) {
    const float* x = (const float*)d_in[0];
    const float* wx = (const float*)d_in[1];
    const float* wy = (const float*)d_in[3];
    const float* Wq = (const float*)d_in[5];
    const float* bq = (const float*)d_in[6];
    const float* Wk = (const float*)d_in[7];
    const float* bk = (const float*)d_in[8];
    const float* Wv = (const float*)d_in[9];
    const float* bv = (const float*)d_in[10];
    const float* Wo = (const float*)d_in[11];
    const float* bo = (const float*)d_in[12];
    const float* gamma = (const float*)d_in[13];
    const float* beta = (const float*)d_in[14];
    float* out = (float*)d_out;

    float *g, *q, *k, *v, *xm, *ym, *part, *stats;
    __half *g16, *h16, *w16;
    cudaGetSymbolAddress((void**)&g, d_g);
    cudaGetSymbolAddress((void**)&g16, d_g16);
    cudaGetSymbolAddress((void**)&h16, d_h16);
    cudaGetSymbolAddress((void**)&q, d_q);
    cudaGetSymbolAddress((void**)&k, d_k);
    cudaGetSymbolAddress((void**)&v, d_v);
    cudaGetSymbolAddress((void**)&w16, d_w16);
    cudaGetSymbolAddress((void**)&xm, d_xm);
    cudaGetSymbolAddress((void**)&ym, d_ym);
    cudaGetSymbolAddress((void**)&part, d_part);
    cudaGetSymbolAddress((void**)&stats, d_stats);

    __half* wq16 = w16;
    __half* wk16 = w16 + (size_t)Dn * Dn;
    __half* wv16 = w16 + 2 * (size_t)Dn * Dn;
    __half* wo16 = w16 + 3 * (size_t)Dn * Dn;

    cudaFuncSetAttribute(gemm_h, cudaFuncAttributeMaxDynamicSharedMemorySize, SMEMB);

    // L1: all weight conversions
    f2h_all_kernel<<<dim3((Dn * Dn / 4) / 256, 4), 256>>>((const float4*)Wq, (const float4*)Wk,
                                                          (const float4*)Wv, (const float4*)Wo,
                                                          (__half2*)w16);
    // L2..L5
    rowcol_kernel<<<Bn + 2048, 128>>>(x, xm, part);
    colfin_xmstats_kernel<<<33, 128>>>(part, ym, xm, wx, stats);
    ymstats_kernel<<<1, 256>>>(ym, wy, stats);
    gmul_kernel<<<(int)(((size_t)Bn * Dn / 4) / 256), 256>>>(x, xm, ym, stats, wx, wy, g, g16);

    // L6..L8: QKV GEMMs (L6 is the ncu -s 5 target)
    dim3 gg(Dn / BN, Bn / BM);  // (32, 128)
    gemm_h<<<gg, 256, SMEMB>>>(g16, wq16, bq, q);
    gemm_h<<<gg, 256, SMEMB>>>(g16, wk16, bk, k);
    gemm_h<<<gg, 256, SMEMB>>>(g16, wv16, bv, v);

    attn_ln_kernel<<<Bn, 128>>>(q, k, v, g, gamma, beta, h16);

    gemm_h<<<gg, 256, SMEMB>>>(h16, wo16, bo, out);
}

// round 6
// speedup vs baseline: 2.7068x; 1.0147x over previous
#include <cuda_runtime.h>
#include <cuda_fp16.h>
#include <cstdint>
#include <math.h>

// Problem dims (fixed by the dataset)
#define Bn 16384
#define Dn 4096
#define Hh 32
#define HDh 128
#define EPSf 1e-5f

// ---- fp16 mma.sync GEMM tiling (2 CTA/SM) -----------------------------------
#define BM 128
#define BN 128
#define BKh 64                 // K elements (fp16) per stage => 128 bytes/row
#define STG 3
#define ROWB 128               // bytes per smem row
#define AST (BM * ROWB)        // 16384
#define BST (BN * ROWB)        // 16384
#define STAGE_B (AST + BST)    // 32768
#define SMEMB (STG * STAGE_B + 1024)  // 99328
#define NKT (4096 / BKh)       // 64

// ---------------- scratch (static device allocations; no cudaMalloc) --------
__device__ float d_g[(size_t)Bn * Dn];
__device__ __half d_g16[(size_t)Bn * Dn];
__device__ __half d_h16[(size_t)Bn * Dn];
__device__ __half d_q16[(size_t)Bn * Dn];
__device__ __half d_k16[(size_t)Bn * Dn];
__device__ __half d_v16[(size_t)Bn * Dn];
__device__ __half d_w16[4][(size_t)Dn * Dn];
__device__ float d_xm[Bn];
__device__ float d_ym[Dn];
__device__ float d_part[64 * Dn];
__device__ float d_stats[4];

// ---------------- helpers -----------------------------------------------------
__device__ __forceinline__ uint32_t smem_u32(const void* p) {
    uint32_t a;
    asm("{ .reg .u64 t; cvta.to.shared.u64 t, %1; cvt.u32.u64 %0, t; }" : "=r"(a) : "l"(p));
    return a;
}
__device__ __forceinline__ void cp_async16(uint32_t saddr, const void* gptr) {
    asm volatile("cp.async.cg.shared.global [%0], [%1], 16;\n" ::"r"(saddr), "l"(gptr));
}
#define LDSM_X4(r, addr)                                                         \
    asm volatile("ldmatrix.sync.aligned.m8n8.x4.shared.b16 {%0,%1,%2,%3}, [%4];" \
                 : "=r"((r)[0]), "=r"((r)[1]), "=r"((r)[2]), "=r"((r)[3])        \
                 : "r"(addr))
__device__ __forceinline__ void mma_h(float* c, const uint32_t* a, uint32_t b0, uint32_t b1) {
    asm volatile(
        "mma.sync.aligned.m16n8k16.row.col.f32.f16.f16.f32 "
        "{%0,%1,%2,%3}, {%4,%5,%6,%7}, {%8,%9}, {%0,%1,%2,%3};\n"
        : "+f"(c[0]), "+f"(c[1]), "+f"(c[2]), "+f"(c[3])
        : "r"(a[0]), "r"(a[1]), "r"(a[2]), "r"(a[3]), "r"(b0), "r"(b1));
}
__device__ __forceinline__ float warp_sum(float v) {
#pragma unroll
    for (int o = 16; o > 0; o >>= 1) v += __shfl_down_sync(0xffffffffu, v, o);
    return v;
}

// ---- L0: rowmean (blocks 0..16383) + colpart (blocks 16384..18431) ----------
__global__ void rowcol_kernel(const float* __restrict__ x, float* __restrict__ xm,
                              float* __restrict__ part) {
    __shared__ float sred[4];
    int t = threadIdx.x;
    if (blockIdx.x < Bn) {
        int b = blockIdx.x;
        size_t off = (size_t)b * Dn;
        float s = 0.f;
        for (int d = t; d < Dn; d += 128) s += x[off + d];
        s = warp_sum(s);
        if ((t & 31) == 0) sred[t >> 5] = s;
        __syncthreads();
        if (t == 0) xm[b] = (sred[0] + sred[1] + sred[2] + sred[3]) * (1.0f / Dn);
    } else {
        int j = blockIdx.x - Bn;       // 0..2047
        int c = (j & 31) * 128 + t;    // column
        int r0 = (j >> 5) * 256;       // row chunk
        float s = 0.f;
        for (int i = 0; i < 256; i++) s += x[(size_t)(r0 + i) * Dn + c];
        part[(size_t)(j >> 5) * Dn + c] = s;
    }
}

// ---- L1: single block: colfin + xm stats + ym stats -------------------------
__global__ void statsall_kernel(const float* __restrict__ part, const float* __restrict__ xm,
                                const float* __restrict__ wx, const float* __restrict__ wy,
                                float* __restrict__ ym, float* __restrict__ stats) {
    __shared__ float sA[32], sB[32], sC[32], sD[32];
    int t = threadIdx.x;  // 1024 threads
    // phase 1: finish column means, accumulate ym stats on the fly
    float ys = 0.f, yss = 0.f;
    for (int c = t; c < Dn; c += 1024) {
        float s = 0.f;
        for (int j = 0; j < 64; j++) s += part[(size_t)j * Dn + c];
        float m = s * (1.0f / Bn);
        ym[c] = m;
        ys += m;
        yss += m * m;
    }
    // phase 2: xm stats
    float xs = 0.f, xss = 0.f;
    for (int i = t; i < Bn; i += 1024) {
        float u = xm[i];
        xs += u;
        xss += u * u;
    }
    xs = warp_sum(xs);
    xss = warp_sum(xss);
    ys = warp_sum(ys);
    yss = warp_sum(yss);
    if ((t & 31) == 0) { sA[t >> 5] = xs; sB[t >> 5] = xss; sC[t >> 5] = ys; sD[t >> 5] = yss; }
    __syncthreads();
    if (t == 0) {
        float XS = 0.f, XSS = 0.f, YS = 0.f, YSS = 0.f;
        for (int j = 0; j < 32; j++) { XS += sA[j]; XSS += sB[j]; YS += sC[j]; YSS += sD[j]; }
        float xmean = XS * (1.0f / Bn);
        float xvar = XSS * (1.0f / Bn) - xmean * xmean;
        float wxv = *wx;
        stats[0] = xmean;
        stats[1] = sqrtf(wxv * wxv * xvar + EPSf) + EPSf;
        float ymean = YS * (1.0f / Dn);
        float yvar = YSS * (1.0f / Dn) - ymean * ymean;
        float wyv = *wy;
        stats[2] = ymean;
        stats[3] = sqrtf(wyv * wyv * yvar + EPSf) + EPSf;
    }
}

// ---- L2: fused gated-multiply (blocks < GMB) + weight f2h (rest) ------------
#define GMB 65536  // gmul blocks: 16M float4 / 256
__global__ void mega_kernel(const float* __restrict__ x, const float* __restrict__ xm,
                            const float* __restrict__ ym, const float* __restrict__ stats,
                            const float* __restrict__ wxp, const float* __restrict__ wyp,
                            float* __restrict__ g, __half* __restrict__ g16,
                            const float4* __restrict__ w0, const float4* __restrict__ w1,
                            const float4* __restrict__ w2, const float4* __restrict__ w3,
                            __half2* __restrict__ wdst) {
    if (blockIdx.x < GMB) {
        size_t i4 = (size_t)blockIdx.x * 256 + threadIdx.x;
        int b = (int)(i4 >> 10);
        int d = (int)((i4 & 1023) << 2);
        float zx = (*wxp) * (xm[b] - stats[0]) / stats[1];
        float gxv = 1.0f / (1.0f + expf(-zx));
        float wy = *wyp, m2 = stats[2], d2 = stats[3];
        float4 xv = *(const float4*)(x + ((size_t)b << 12) + d);
        float4 gv;
        gv.x = xv.x * gxv / (1.0f + expf(-wy * (ym[d + 0] - m2) / d2));
        gv.y = xv.y * gxv / (1.0f + expf(-wy * (ym[d + 1] - m2) / d2));
        gv.z = xv.z * gxv / (1.0f + expf(-wy * (ym[d + 2] - m2) / d2));
        gv.w = xv.w * gxv / (1.0f + expf(-wy * (ym[d + 3] - m2) / d2));
        *(float4*)(g + ((size_t)b << 12) + d) = gv;
        *(__half2*)(g16 + ((size_t)b << 12) + d) = __floats2half2_rn(gv.x, gv.y);
        *(__half2*)(g16 + ((size_t)b << 12) + d + 2) = __floats2half2_rn(gv.z, gv.w);
    } else {
        const float4* srcs[4] = {w0, w1, w2, w3};
        int j = blockIdx.x - GMB;          // 0..65535
        int wsel = j >> 14;                // 16384 blocks per weight
        size_t i = (size_t)(j & 16383) * 256 + threadIdx.x;   // float4 idx within weight
        float4 v = srcs[wsel][i];
        __half2* d = wdst + (size_t)wsel * ((size_t)Dn * Dn / 2) + 2 * i;
        d[0] = __floats2half2_rn(v.x, v.y);
        d[1] = __floats2half2_rn(v.z, v.w);
    }
}

// ---------------- fp16 tensor-core GEMM: C[M,4096] = A @ W^T + bias ----------
template <typename OutT>
__global__ __launch_bounds__(256, 2) void gemm_h(const __half* __restrict__ A,
                                                 const __half* __restrict__ W,
                                                 const float* __restrict__ bias,
                                                 OutT* __restrict__ C) {
    extern __shared__ char smem[];
    const uint32_t sbase = (smem_u32(smem) + 1023u) & ~1023u;
    const int tid = threadIdx.x;
    const int wid = tid >> 5, lane = tid & 31;
    const int wm = wid >> 2, wn = wid & 3;     // warp grid 2 x 4 -> 64x32 per warp
    const int grp = lane >> 2, tg = lane & 3;
    const int m0 = blockIdx.y * BM;
    const int n0 = blockIdx.x * BN;

    auto load_tile = [&](int s, int k0) {
        uint32_t sA = sbase + s * STAGE_B;
        uint32_t sB = sA + AST;
#pragma unroll
        for (int i = 0; i < 4; i++) {                 // A: 1024 chunks of 16B
            int c = tid + i * 256;
            int row = c >> 3, kc = c & 7;
            uint32_t off = row * ROWB + ((kc << 4) ^ ((row & 7) << 4));
            cp_async16(sA + off, A + (size_t)(m0 + row) * 4096 + k0 + kc * 8);
        }
#pragma unroll
        for (int i = 0; i < 4; i++) {                 // B: 1024 chunks of 16B
            int c = tid + i * 256;
            int row = c >> 3, kc = c & 7;
            uint32_t off = row * ROWB + ((kc << 4) ^ ((row & 7) << 4));
            cp_async16(sB + off, W + (size_t)(n0 + row) * 4096 + k0 + kc * 8);
        }
        asm volatile("cp.async.commit_group;\n" ::: "memory");
    };

    float acc[4][4][4];
#pragma unroll
    for (int mi = 0; mi < 4; mi++)
#pragma unroll
        for (int ni = 0; ni < 4; ni++)
#pragma unroll
            for (int r = 0; r < 4; r++) acc[mi][ni][r] = 0.f;

    load_tile(0, 0);
    load_tile(1, BKh);

    // single-barrier mainloop: wait -> sync -> load(kt+2) -> compute(kt)
    int load_st = 2;   // next stage slot to fill
    int comp_st = 0;   // stage to compute
    for (int kt = 0; kt < NKT; kt++) {
        asm volatile("cp.async.wait_group 1;\n" ::: "memory");
        __syncthreads();   // all warps done computing stage (kt-1); stage kt data visible

        int nxt = kt + 2;
        if (nxt < NKT) {
            load_tile(load_st, nxt * BKh);     // overwrites stage of kt-1 (safe post-sync)
            if (++load_st == STG) load_st = 0;
        } else {
            asm volatile("cp.async.commit_group;\n" ::: "memory");  // keep group count exact
        }

        uint32_t sA = sbase + comp_st * STAGE_B;
        uint32_t sB = sA + AST;
#pragma unroll
        for (int step = 0; step < 4; step++) {
            const uint32_t kx = step * 32 + ((lane >> 4) << 4);
            uint32_t afr[4][4], bfr[2][4];
#pragma unroll
            for (int mi = 0; mi < 4; mi++) {
                int row = wm * 64 + mi * 16 + (lane & 15);
                LDSM_X4(afr[mi], sA + row * ROWB + (kx ^ ((row & 7) << 4)));
            }
#pragma unroll
            for (int p = 0; p < 2; p++) {
                int row = wn * 32 + p * 16 + (lane & 15);
                LDSM_X4(bfr[p], sB + row * ROWB + (kx ^ ((row & 7) << 4)));
            }
#pragma unroll
            for (int mi = 0; mi < 4; mi++)
#pragma unroll
                for (int ni = 0; ni < 4; ni++) {
                    int p = ni >> 1, hi = ni & 1;
                    mma_h(acc[mi][ni], afr[mi], bfr[p][hi], bfr[p][hi + 2]);
                }
        }
        if (++comp_st == STG) comp_st = 0;
    }

    // epilogue: + bias
#pragma unroll
    for (int mi = 0; mi < 4; mi++) {
#pragma unroll
        for (int ni = 0; ni < 4; ni++) {
            int row = m0 + wm * 64 + mi * 16 + grp;
            int col = n0 + wn * 32 + ni * 8 + tg * 2;
            float b0 = __ldg(bias + col), b1 = __ldg(bias + col + 1);
            float c00 = acc[mi][ni][0] + b0, c01 = acc[mi][ni][1] + b1;
            float c10 = acc[mi][ni][2] + b0, c11 = acc[mi][ni][3] + b1;
            if (sizeof(OutT) == 4) {
                *(float2*)&((float*)C)[(size_t)row * Dn + col] = make_float2(c00, c01);
                *(float2*)&((float*)C)[(size_t)(row + 8) * Dn + col] = make_float2(c10, c11);
            } else {
                *(__half2*)&((__half*)C)[(size_t)row * Dn + col] = __floats2half2_rn(c00, c01);
                *(__half2*)&((__half*)C)[(size_t)(row + 8) * Dn + col] = __floats2half2_rn(c10, c11);
            }
        }
    }
}

// ---------------- stage C: per-row scalar attention + residual + LN ----------
__global__ void attn_ln_kernel(const __half* __restrict__ Q, const __half* __restrict__ K,
                               const __half* __restrict__ V, const float* __restrict__ G,
                               const float* __restrict__ gamma, const float* __restrict__ beta,
                               __half* __restrict__ Hout) {
    __shared__ float sval[Dn];
    __shared__ float swarp[Hh][4];
    __shared__ float sw[Hh];
    __shared__ float sredA[4], sredB[4];
    __shared__ float sstat[2];

    int b = blockIdx.x, t = threadIdx.x;
    int warp = t >> 5, lane = t & 31;
    size_t off = (size_t)b * Dn;

#pragma unroll 1
    for (int i = 0; i < Hh; i++) {
        int d = i * HDh + t;
        float p = __half2float(Q[off + d]) * __half2float(K[off + d]);
        p = warp_sum(p);
        if (lane == 0) swarp[i][warp] = p;
    }
    __syncthreads();
    if (t < Hh) {
        float s = (swarp[t][0] + swarp[t][1] + swarp[t][2] + swarp[t][3]) * 0.08838834764831845f;
        float m = s;
#pragma unroll
        for (int o = 16; o > 0; o >>= 1) m = fmaxf(m, __shfl_xor_sync(0xffffffffu, m, o));
        float e = expf(s - m);
        float sum = e;
#pragma unroll
        for (int o = 16; o > 0; o >>= 1) sum += __shfl_xor_sync(0xffffffffu, sum, o);
        sw[t] = e / sum;
    }
    __syncthreads();

    float s1 = 0.f, s2 = 0.f;
#pragma unroll 1
    for (int i = 0; i < Hh; i++) {
        int d = i * HDh + t;
        float val = sw[i] * __half2float(V[off + d]) + G[off + d];
        sval[d] = val;
        s1 += val;
        s2 += val * val;
    }
    s1 = warp_sum(s1);
    s2 = warp_sum(s2);
    if (lane == 0) { sredA[warp] = s1; sredB[warp] = s2; }
    __syncthreads();
    if (t == 0) {
        float S1 = sredA[0] + sredA[1] + sredA[2] + sredA[3];
        float S2 = sredB[0] + sredB[1] + sredB[2] + sredB[3];
        float mean = S1 * (1.0f / Dn);
        float var = S2 * (1.0f / Dn) - mean * mean;
        sstat[0] = mean;
        sstat[1] = 1.0f / sqrtf(var + EPSf);
    }
    __syncthreads();
    float mean = sstat[0], rstd = sstat[1];
#pragma unroll 1
    for (int i = 0; i < Hh; i++) {
        int d = i * HDh + t;
        Hout[off + d] = __float2half((sval[d] - mean) * rstd * gamma[d] + beta[d]);
    }
}

// ---------------- launch ------------------------------------------------------
extern "C" void kernel_launch(void* const* d_in, const int* in_sizes, int n_in,
                              void* d_out, int out_size) {
    const float* x = (const float*)d_in[0];
    const float* wx = (const float*)d_in[1];
    const float* wy = (const float*)d_in[3];
    const float* Wq = (const float*)d_in[5];
    const float* bq = (const float*)d_in[6];
    const float* Wk = (const float*)d_in[7];
    const float* bk = (const float*)d_in[8];
    const float* Wv = (const float*)d_in[9];
    const float* bv = (const float*)d_in[10];
    const float* Wo = (const float*)d_in[11];
    const float* bo = (const float*)d_in[12];
    const float* gamma = (const float*)d_in[13];
    const float* beta = (const float*)d_in[14];
    float* out = (float*)d_out;

    float *g, *xm, *ym, *part, *stats;
    __half *g16, *h16, *q16, *k16, *v16, *w16;
    cudaGetSymbolAddress((void**)&g, d_g);
    cudaGetSymbolAddress((void**)&g16, d_g16);
    cudaGetSymbolAddress((void**)&h16, d_h16);
    cudaGetSymbolAddress((void**)&q16, d_q16);
    cudaGetSymbolAddress((void**)&k16, d_k16);
    cudaGetSymbolAddress((void**)&v16, d_v16);
    cudaGetSymbolAddress((void**)&w16, d_w16);
    cudaGetSymbolAddress((void**)&xm, d_xm);
    cudaGetSymbolAddress((void**)&ym, d_ym);
    cudaGetSymbolAddress((void**)&part, d_part);
    cudaGetSymbolAddress((void**)&stats, d_stats);

    __half* wq16 = w16;
    __half* wk16 = w16 + (size_t)Dn * Dn;
    __half* wv16 = w16 + 2 * (size_t)Dn * Dn;
    __half* wo16 = w16 + 3 * (size_t)Dn * Dn;

    cudaFuncSetAttribute(gemm_h<__half>, cudaFuncAttributeMaxDynamicSharedMemorySize, SMEMB);
    cudaFuncSetAttribute(gemm_h<float>, cudaFuncAttributeMaxDynamicSharedMemorySize, SMEMB);

    // L0..L2
    rowcol_kernel<<<Bn + 2048, 128>>>(x, xm, part);
    statsall_kernel<<<1, 1024>>>(part, xm, wx, wy, ym, stats);
    mega_kernel<<<2 * GMB, 256>>>(x, xm, ym, stats, wx, wy, g, g16,
                                  (const float4*)Wq, (const float4*)Wk, (const float4*)Wv,
                                  (const float4*)Wo, (__half2*)w16);

    // L3..L5: QKV GEMMs (L3 = ncu capture target)
    dim3 gg(Dn / BN, Bn / BM);  // (32, 128)
    gemm_h<__half><<<gg, 256, SMEMB>>>(g16, wq16, bq, q16);
    gemm_h<__half><<<gg, 256, SMEMB>>>(g16, wk16, bk, k16);
    gemm_h<__half><<<gg, 256, SMEMB>>>(g16, wv16, bv, v16);

    // L6: attention + LN
    attn_ln_kernel<<<Bn, 128>>>(q16, k16, v16, g, gamma, beta, h16);

    // L7: output GEMM (fp32 out)
    gemm_h<float><<<gg, 256, SMEMB>>>(h16, wo16, bo, out);
}

// round 7
// speedup vs baseline: 3.0762x; 1.1365x over previous
#include <cuda_runtime.h>
#include <cuda_fp16.h>
#include <cstdint>
#include <math.h>

// Problem dims (fixed by the dataset)
#define Bn 16384
#define Dn 4096
#define Hh 32
#define HDh 128
#define EPSf 1e-5f

// ---- fp16 mma.sync GEMM tiling (2 CTA/SM) -----------------------------------
#define BM 128
#define BN 128
#define BKh 64                 // K elements (fp16) per stage => 128 bytes/row
#define STG 3
#define ROWB 128               // bytes per smem row
#define AST (BM * ROWB)        // 16384
#define BST (BN * ROWB)        // 16384
#define STAGE_B (AST + BST)    // 32768
#define SMEMB (STG * STAGE_B + 1024)  // 99328
#define NKT (4096 / BKh)       // 64

// ---------------- scratch (static device allocations; no cudaMalloc) --------
__device__ float d_g[(size_t)Bn * Dn];
__device__ __half d_g16[(size_t)Bn * Dn];
__device__ __half d_h16[(size_t)Bn * Dn];
__device__ __half d_q16[(size_t)Bn * Dn];
__device__ __half d_k16[(size_t)Bn * Dn];
__device__ __half d_v16[(size_t)Bn * Dn];
__device__ __half d_w16[4][(size_t)Dn * Dn];
__device__ float d_xm[Bn];
__device__ float d_ym[Dn];
__device__ float d_part[64 * Dn];
__device__ float d_stats[4];

// ---------------- helpers -----------------------------------------------------
__device__ __forceinline__ uint32_t smem_u32(const void* p) {
    uint32_t a;
    asm("{ .reg .u64 t; cvta.to.shared.u64 t, %1; cvt.u32.u64 %0, t; }" : "=r"(a) : "l"(p));
    return a;
}
__device__ __forceinline__ void cp_async16(uint32_t saddr, const void* gptr) {
    asm volatile("cp.async.cg.shared.global [%0], [%1], 16;\n" ::"r"(saddr), "l"(gptr));
}
#define LDSM_X4(r, addr)                                                         \
    asm volatile("ldmatrix.sync.aligned.m8n8.x4.shared.b16 {%0,%1,%2,%3}, [%4];" \
                 : "=r"((r)[0]), "=r"((r)[1]), "=r"((r)[2]), "=r"((r)[3])        \
                 : "r"(addr))
__device__ __forceinline__ void mma_h(float* c, const uint32_t* a, uint32_t b0, uint32_t b1) {
    asm volatile(
        "mma.sync.aligned.m16n8k16.row.col.f32.f16.f16.f32 "
        "{%0,%1,%2,%3}, {%4,%5,%6,%7}, {%8,%9}, {%0,%1,%2,%3};\n"
        : "+f"(c[0]), "+f"(c[1]), "+f"(c[2]), "+f"(c[3])
        : "r"(a[0]), "r"(a[1]), "r"(a[2]), "r"(a[3]), "r"(b0), "r"(b1));
}
__device__ __forceinline__ float warp_sum(float v) {
#pragma unroll
    for (int o = 16; o > 0; o >>= 1) v += __shfl_down_sync(0xffffffffu, v, o);
    return v;
}

// ---- L0: rowmean (blocks 0..16383) + colpart (blocks 16384..18431) ----------
__global__ void rowcol_kernel(const float* __restrict__ x, float* __restrict__ xm,
                              float* __restrict__ part) {
    __shared__ float sred[4];
    int t = threadIdx.x;
    if (blockIdx.x < Bn) {
        int b = blockIdx.x;
        size_t off = (size_t)b * Dn;
        float s = 0.f;
        for (int d = t; d < Dn; d += 128) s += x[off + d];
        s = warp_sum(s);
        if ((t & 31) == 0) sred[t >> 5] = s;
        __syncthreads();
        if (t == 0) xm[b] = (sred[0] + sred[1] + sred[2] + sred[3]) * (1.0f / Dn);
    } else {
        int j = blockIdx.x - Bn;       // 0..2047
        int c = (j & 31) * 128 + t;    // column
        int r0 = (j >> 5) * 256;       // row chunk
        float s = 0.f;
        for (int i = 0; i < 256; i++) s += x[(size_t)(r0 + i) * Dn + c];
        part[(size_t)(j >> 5) * Dn + c] = s;
    }
}

// ---- L1: single block: colfin + xm stats + ym stats -------------------------
__global__ void statsall_kernel(const float* __restrict__ part, const float* __restrict__ xm,
                                const float* __restrict__ wx, const float* __restrict__ wy,
                                float* __restrict__ ym, float* __restrict__ stats) {
    __shared__ float sA[32], sB[32], sC[32], sD[32];
    int t = threadIdx.x;  // 1024 threads
    float ys = 0.f, yss = 0.f;
    for (int c = t; c < Dn; c += 1024) {
        float s = 0.f;
        for (int j = 0; j < 64; j++) s += part[(size_t)j * Dn + c];
        float m = s * (1.0f / Bn);
        ym[c] = m;
        ys += m;
        yss += m * m;
    }
    float xs = 0.f, xss = 0.f;
    for (int i = t; i < Bn; i += 1024) {
        float u = xm[i];
        xs += u;
        xss += u * u;
    }
    xs = warp_sum(xs);
    xss = warp_sum(xss);
    ys = warp_sum(ys);
    yss = warp_sum(yss);
    if ((t & 31) == 0) { sA[t >> 5] = xs; sB[t >> 5] = xss; sC[t >> 5] = ys; sD[t >> 5] = yss; }
    __syncthreads();
    if (t == 0) {
        float XS = 0.f, XSS = 0.f, YS = 0.f, YSS = 0.f;
        for (int j = 0; j < 32; j++) { XS += sA[j]; XSS += sB[j]; YS += sC[j]; YSS += sD[j]; }
        float xmean = XS * (1.0f / Bn);
        float xvar = XSS * (1.0f / Bn) - xmean * xmean;
        float wxv = *wx;
        stats[0] = xmean;
        stats[1] = sqrtf(wxv * wxv * xvar + EPSf) + EPSf;
        float ymean = YS * (1.0f / Dn);
        float yvar = YSS * (1.0f / Dn) - ymean * ymean;
        float wyv = *wy;
        stats[2] = ymean;
        stats[3] = sqrtf(wyv * wyv * yvar + EPSf) + EPSf;
    }
}

// ---- L2: fused gated-multiply (blocks < GMB) + weight f2h (rest) ------------
#define GMB 65536  // gmul blocks: 16M float4 / 256
__global__ void mega_kernel(const float* __restrict__ x, const float* __restrict__ xm,
                            const float* __restrict__ ym, const float* __restrict__ stats,
                            const float* __restrict__ wxp, const float* __restrict__ wyp,
                            float* __restrict__ g, __half* __restrict__ g16,
                            const float4* __restrict__ w0, const float4* __restrict__ w1,
                            const float4* __restrict__ w2, const float4* __restrict__ w3,
                            __half2* __restrict__ wdst) {
    if (blockIdx.x < GMB) {
        size_t i4 = (size_t)blockIdx.x * 256 + threadIdx.x;
        int b = (int)(i4 >> 10);
        int d = (int)((i4 & 1023) << 2);
        float zx = (*wxp) * (xm[b] - stats[0]) / stats[1];
        float gxv = 1.0f / (1.0f + expf(-zx));
        float wy = *wyp, m2 = stats[2], d2 = stats[3];
        float4 xv = *(const float4*)(x + ((size_t)b << 12) + d);
        float4 gv;
        gv.x = xv.x * gxv / (1.0f + expf(-wy * (ym[d + 0] - m2) / d2));
        gv.y = xv.y * gxv / (1.0f + expf(-wy * (ym[d + 1] - m2) / d2));
        gv.z = xv.z * gxv / (1.0f + expf(-wy * (ym[d + 2] - m2) / d2));
        gv.w = xv.w * gxv / (1.0f + expf(-wy * (ym[d + 3] - m2) / d2));
        *(float4*)(g + ((size_t)b << 12) + d) = gv;
        *(__half2*)(g16 + ((size_t)b << 12) + d) = __floats2half2_rn(gv.x, gv.y);
        *(__half2*)(g16 + ((size_t)b << 12) + d + 2) = __floats2half2_rn(gv.z, gv.w);
    } else {
        const float4* srcs[4] = {w0, w1, w2, w3};
        int j = blockIdx.x - GMB;          // 0..65535
        int wsel = j >> 14;                // 16384 blocks per weight
        size_t i = (size_t)(j & 16383) * 256 + threadIdx.x;
        float4 v = srcs[wsel][i];
        __half2* d = wdst + (size_t)wsel * ((size_t)Dn * Dn / 2) + 2 * i;
        d[0] = __floats2half2_rn(v.x, v.y);
        d[1] = __floats2half2_rn(v.z, v.w);
    }
}

// ---------------- fp16 tensor-core GEMM: C[M,4096] = A @ W^T + bias ----------
// Pipelined: frag double-buffer + cross-stage prefetch; 1 sync + 1 wait per ktile.
template <typename OutT>
__global__ __launch_bounds__(256, 2) void gemm_h(const __half* __restrict__ A,
                                                 const __half* __restrict__ W,
                                                 const float* __restrict__ bias,
                                                 OutT* __restrict__ C) {
    extern __shared__ char smem[];
    const uint32_t sbase = (smem_u32(smem) + 1023u) & ~1023u;
    const int tid = threadIdx.x;
    const int wid = tid >> 5, lane = tid & 31;
    const int wm = wid >> 2, wn = wid & 3;     // warp grid 2 x 4 -> 64x32 per warp
    const int grp = lane >> 2, tg = lane & 3;
    const int m0 = blockIdx.y * BM;
    const int n0 = blockIdx.x * BN;

    // per-warp LDSM base addresses (swizzle folded; per-step just XOR (step<<5))
    const int lh = (lane >> 4) << 4;
    uint32_t baseA[4], baseB[2];
#pragma unroll
    for (int mi = 0; mi < 4; mi++) {
        int row = wm * 64 + mi * 16 + (lane & 15);
        baseA[mi] = (uint32_t)(row * ROWB) + (uint32_t)(lh ^ ((row & 7) << 4));
    }
#pragma unroll
    for (int p = 0; p < 2; p++) {
        int row = wn * 32 + p * 16 + (lane & 15);
        baseB[p] = (uint32_t)(AST + row * ROWB) + (uint32_t)(lh ^ ((row & 7) << 4));
    }

    auto load_tile = [&](uint32_t stage_base, int k0) {
#pragma unroll
        for (int i = 0; i < 4; i++) {                 // A: 1024 chunks of 16B
            int c = tid + i * 256;
            int row = c >> 3, kc = c & 7;
            uint32_t off = row * ROWB + ((kc << 4) ^ ((row & 7) << 4));
            cp_async16(stage_base + off, A + (size_t)(m0 + row) * 4096 + k0 + kc * 8);
        }
#pragma unroll
        for (int i = 0; i < 4; i++) {                 // B: 1024 chunks of 16B
            int c = tid + i * 256;
            int row = c >> 3, kc = c & 7;
            uint32_t off = AST + row * ROWB + ((kc << 4) ^ ((row & 7) << 4));
            cp_async16(stage_base + off, W + (size_t)(n0 + row) * 4096 + k0 + kc * 8);
        }
        asm volatile("cp.async.commit_group;\n" ::: "memory");
    };

    uint32_t af[2][4][4], bf[2][2][4];

    auto do_ldsm = [&](uint32_t (&ab)[4][4], uint32_t (&bb)[2][4], uint32_t sb, uint32_t stx) {
#pragma unroll
        for (int mi = 0; mi < 4; mi++) LDSM_X4(ab[mi], (sb + baseA[mi]) ^ stx);
#pragma unroll
        for (int p = 0; p < 2; p++) LDSM_X4(bb[p], (sb + baseB[p]) ^ stx);
    };

    float acc[4][4][4];
#pragma unroll
    for (int mi = 0; mi < 4; mi++)
#pragma unroll
        for (int ni = 0; ni < 4; ni++)
#pragma unroll
            for (int r = 0; r < 4; r++) acc[mi][ni][r] = 0.f;

    auto do_mma = [&](uint32_t (&ab)[4][4], uint32_t (&bb)[2][4]) {
#pragma unroll
        for (int mi = 0; mi < 4; mi++)
#pragma unroll
            for (int ni = 0; ni < 4; ni++) {
                int p = ni >> 1, hi = ni & 1;
                mma_h(acc[mi][ni], ab[mi], bb[p][hi], bb[p][hi + 2]);
            }
    };

    // prologue: fill all 3 stages, land stage 0, prefetch (kt=0, step=0) frags
    load_tile(sbase, 0);
    load_tile(sbase + STAGE_B, BKh);
    load_tile(sbase + 2 * STAGE_B, 2 * BKh);
    asm volatile("cp.async.wait_group 2;\n" ::: "memory");
    __syncthreads();
    do_ldsm(af[0], bf[0], sbase, 0);

    uint32_t scur = sbase;                 // stage holding data kt
    uint32_t snxt = sbase + STAGE_B;       // stage holding data kt+1
    const uint32_t slast = sbase + 2 * STAGE_B;

    for (int kt = 0; kt < NKT; kt++) {
        // steps 0..2: prefetch next step's frags, then MMA current
#pragma unroll
        for (int step = 0; step < 3; step++) {
            const int cb = step & 1;
            do_ldsm(af[cb ^ 1], bf[cb ^ 1], scur, (uint32_t)((step + 1) << 5));
            do_mma(af[cb], bf[cb]);
        }
        // step 3: drain copies, barrier, refill stage kt's slot, prefetch (kt+1,0)
        asm volatile("cp.async.wait_group 0;\n" ::: "memory");
        __syncthreads();   // stage kt fully consumed by all warps; stage kt+1 published
        if (kt + 3 < NKT) load_tile(scur, (kt + 3) * BKh);
        do_ldsm(af[0], bf[0], snxt, 0);
        do_mma(af[1], bf[1]);

        // rotate stage pointers
        uint32_t t2 = snxt;
        snxt = (snxt == slast) ? sbase : snxt + STAGE_B;
        scur = t2;
    }

    // epilogue: + bias
#pragma unroll
    for (int mi = 0; mi < 4; mi++) {
#pragma unroll
        for (int ni = 0; ni < 4; ni++) {
            int row = m0 + wm * 64 + mi * 16 + grp;
            int col = n0 + wn * 32 + ni * 8 + tg * 2;
            float b0 = __ldg(bias + col), b1 = __ldg(bias + col + 1);
            float c00 = acc[mi][ni][0] + b0, c01 = acc[mi][ni][1] + b1;
            float c10 = acc[mi][ni][2] + b0, c11 = acc[mi][ni][3] + b1;
            if (sizeof(OutT) == 4) {
                *(float2*)&((float*)C)[(size_t)row * Dn + col] = make_float2(c00, c01);
                *(float2*)&((float*)C)[(size_t)(row + 8) * Dn + col] = make_float2(c10, c11);
            } else {
                *(__half2*)&((__half*)C)[(size_t)row * Dn + col] = __floats2half2_rn(c00, c01);
                *(__half2*)&((__half*)C)[(size_t)(row + 8) * Dn + col] = __floats2half2_rn(c10, c11);
            }
        }
    }
}

// ---------------- stage C: per-row scalar attention + residual + LN ----------
__global__ void attn_ln_kernel(const __half* __restrict__ Q, const __half* __restrict__ K,
                               const __half* __restrict__ V, const float* __restrict__ G,
                               const float* __restrict__ gamma, const float* __restrict__ beta,
                               __half* __restrict__ Hout) {
    __shared__ float sval[Dn];
    __shared__ float swarp[Hh][4];
    __shared__ float sw[Hh];
    __shared__ float sredA[4], sredB[4];
    __shared__ float sstat[2];

    int b = blockIdx.x, t = threadIdx.x;
    int warp = t >> 5, lane = t & 31;
    size_t off = (size_t)b * Dn;

#pragma unroll 1
    for (int i = 0; i < Hh; i++) {
        int d = i * HDh + t;
        float p = __half2float(Q[off + d]) * __half2float(K[off + d]);
        p = warp_sum(p);
        if (lane == 0) swarp[i][warp] = p;
    }
    __syncthreads();
    if (t < Hh) {
        float s = (swarp[t][0] + swarp[t][1] + swarp[t][2] + swarp[t][3]) * 0.08838834764831845f;
        float m = s;
#pragma unroll
        for (int o = 16; o > 0; o >>= 1) m = fmaxf(m, __shfl_xor_sync(0xffffffffu, m, o));
        float e = expf(s - m);
        float sum = e;
#pragma unroll
        for (int o = 16; o > 0; o >>= 1) sum += __shfl_xor_sync(0xffffffffu, sum, o);
        sw[t] = e / sum;
    }
    __syncthreads();

    float s1 = 0.f, s2 = 0.f;
#pragma unroll 1
    for (int i = 0; i < Hh; i++) {
        int d = i * HDh + t;
        float val = sw[i] * __half2float(V[off + d]) + G[off + d];
        sval[d] = val;
        s1 += val;
        s2 += val * val;
    }
    s1 = warp_sum(s1);
    s2 = warp_sum(s2);
    if (lane == 0) { sredA[warp] = s1; sredB[warp] = s2; }
    __syncthreads();
    if (t == 0) {
        float S1 = sredA[0] + sredA[1] + sredA[2] + sredA[3];
        float S2 = sredB[0] + sredB[1] + sredB[2] + sredB[3];
        float mean = S1 * (1.0f / Dn);
        float var = S2 * (1.0f / Dn) - mean * mean;
        sstat[0] = mean;
        sstat[1] = 1.0f / sqrtf(var + EPSf);
    }
    __syncthreads();
    float mean = sstat[0], rstd = sstat[1];
#pragma unroll 1
    for (int i = 0; i < Hh; i++) {
        int d = i * HDh + t;
        Hout[off + d] = __float2half((sval[d] - mean) * rstd * gamma[d] + beta[d]);
    }
}

// ---------------- launch ------------------------------------------------------
extern "C" void kernel_launch(void* const* d_in, const int* in_sizes, int n_in,
                              void* d_out, int out_size) {
    const float* x = (const float*)d_in[0];
    const float* wx = (const float*)d_in[1];
    const float* wy = (const float*)d_in[3];
    const float* Wq = (const float*)d_in[5];
    const float* bq = (const float*)d_in[6];
    const float* Wk = (const float*)d_in[7];
    const float* bk = (const float*)d_in[8];
    const float* Wv = (const float*)d_in[9];
    const float* bv = (const float*)d_in[10];
    const float* Wo = (const float*)d_in[11];
    const float* bo = (const float*)d_in[12];
    const float* gamma = (const float*)d_in[13];
    const float* beta = (const float*)d_in[14];
    float* out = (float*)d_out;

    float *g, *xm, *ym, *part, *stats;
    __half *g16, *h16, *q16, *k16, *v16, *w16;
    cudaGetSymbolAddress((void**)&g, d_g);
    cudaGetSymbolAddress((void**)&g16, d_g16);
    cudaGetSymbolAddress((void**)&h16, d_h16);
    cudaGetSymbolAddress((void**)&q16, d_q16);
    cudaGetSymbolAddress((void**)&k16, d_k16);
    cudaGetSymbolAddress((void**)&v16, d_v16);
    cudaGetSymbolAddress((void**)&w16, d_w16);
    cudaGetSymbolAddress((void**)&xm, d_xm);
    cudaGetSymbolAddress((void**)&ym, d_ym);
    cudaGetSymbolAddress((void**)&part, d_part);
    cudaGetSymbolAddress((void**)&stats, d_stats);

    __half* wq16 = w16;
    __half* wk16 = w16 + (size_t)Dn * Dn;
    __half* wv16 = w16 + 2 * (size_t)Dn * Dn;
    __half* wo16 = w16 + 3 * (size_t)Dn * Dn;

    cudaFuncSetAttribute(gemm_h<__half>, cudaFuncAttributeMaxDynamicSharedMemorySize, SMEMB);
    cudaFuncSetAttribute(gemm_h<float>, cudaFuncAttributeMaxDynamicSharedMemorySize, SMEMB);

    // L0..L2
    rowcol_kernel<<<Bn + 2048, 128>>>(x, xm, part);
    statsall_kernel<<<1, 1024>>>(part, xm, wx, wy, ym, stats);
    mega_kernel<<<2 * GMB, 256>>>(x, xm, ym, stats, wx, wy, g, g16,
                                  (const float4*)Wq, (const float4*)Wk, (const float4*)Wv,
                                  (const float4*)Wo, (__half2*)w16);

    // L3..L5: QKV GEMMs (L3 = ncu capture target)
    dim3 gg(Dn / BN, Bn / BM);  // (32, 128)
    gemm_h<__half><<<gg, 256, SMEMB>>>(g16, wq16, bq, q16);
    gemm_h<__half><<<gg, 256, SMEMB>>>(g16, wk16, bk, k16);
    gemm_h<__half><<<gg, 256, SMEMB>>>(g16, wv16, bv, v16);

    // L6: attention + LN
    attn_ln_kernel<<<Bn, 128>>>(q16, k16, v16, g, gamma, beta, h16);

    // L7: output GEMM (fp32 out)
    gemm_h<float><<<gg, 256, SMEMB>>>(h16, wo16, bo, out);
}